// round 1
// baseline (speedup 1.0000x reference)
#include <cuda_runtime.h>
#include <cuda_bf16.h>

// Problem constants
#define BB 2
#define SS 2048
#define EE 1024
#define HH 16
#define DD 64
#define MM (BB*SS)          // 4096 rows for all GEMMs

// Scratch (device globals; no allocation allowed)
__device__ float g_Qt[BB*HH*DD*SS];   // [bh][d][s]  (d-major for attention)
__device__ float g_Kt[BB*HH*DD*SS];   // [bh][d][s]
__device__ float g_V [BB*HH*SS*DD];   // [bh][s][d]
__device__ float g_ctx[BB*SS*EE];     // [b*s][e]

// ---------------------------------------------------------------------------
// Generic 128x128x16 SGEMM body: C[M=4096, N=1024] = A[4096,1024] @ W[:, wcol0:wcol0+1024] + bias
// mode 0 -> g_Qt (d-major), 1 -> g_Kt (d-major), 2 -> g_V (s-major), 3 -> Cout row-major
// ---------------------------------------------------------------------------
__device__ __forceinline__ void gemm_body(
    const float* __restrict__ A,
    const float* __restrict__ W, int ldw, int wcol0,
    const float* __restrict__ bias, int biasoff,
    float* __restrict__ Cout, int mode)
{
    __shared__ float As[16][132];   // [k][m], padded
    __shared__ float Bs[16][128];   // [k][n]

    const int tid = threadIdx.x;
    const int ty = tid >> 4;        // 0..15
    const int tx = tid & 15;        // 0..15
    const int m0 = blockIdx.y << 7;
    const int n0 = blockIdx.x << 7;

    float acc[8][8] = {};

    for (int kt = 0; kt < EE; kt += 16) {
        // load A tile (128 rows x 16 cols), transpose into As[k][m]
        #pragma unroll
        for (int it = 0; it < 2; ++it) {
            int f = tid + (it << 8);        // 0..511
            int r = f >> 2;                 // 0..127
            int c = (f & 3) << 2;           // 0,4,8,12
            float4 v = *(const float4*)(A + (size_t)(m0 + r) * EE + kt + c);
            As[c + 0][r] = v.x;
            As[c + 1][r] = v.y;
            As[c + 2][r] = v.z;
            As[c + 3][r] = v.w;
        }
        // load W tile (16 rows x 128 cols)
        #pragma unroll
        for (int it = 0; it < 2; ++it) {
            int f = tid + (it << 8);
            int r = f >> 5;                 // 0..15
            int c = (f & 31) << 2;          // 0..124
            *(float4*)&Bs[r][c] =
                *(const float4*)(W + (size_t)(kt + r) * ldw + wcol0 + n0 + c);
        }
        __syncthreads();

        #pragma unroll
        for (int kk = 0; kk < 16; ++kk) {
            float a[8], b[8];
            *(float4*)&a[0] = *(float4*)&As[kk][ty * 8];
            *(float4*)&a[4] = *(float4*)&As[kk][ty * 8 + 4];
            *(float4*)&b[0] = *(float4*)&Bs[kk][tx * 8];
            *(float4*)&b[4] = *(float4*)&Bs[kk][tx * 8 + 4];
            #pragma unroll
            for (int i = 0; i < 8; ++i)
                #pragma unroll
                for (int j = 0; j < 8; ++j)
                    acc[i][j] = fmaf(a[i], b[j], acc[i][j]);
        }
        __syncthreads();
    }

    // epilogue
    #pragma unroll
    for (int i = 0; i < 8; ++i) {
        int m = m0 + ty * 8 + i;
        int b = m >> 11;            // /2048
        int s = m & (SS - 1);
        #pragma unroll
        for (int j = 0; j < 8; ++j) {
            int n = n0 + tx * 8 + j;
            float val = acc[i][j] + bias[biasoff + n];
            int h = n >> 6;         // /64
            int d = n & 63;
            if (mode == 0)
                g_Qt[(size_t)(((b << 4) + h) * DD + d) * SS + s] = val;
            else if (mode == 1)
                g_Kt[(size_t)(((b << 4) + h) * DD + d) * SS + s] = val;
            else if (mode == 2)
                g_V[(size_t)(((b << 4) + h) * SS + s) * DD + d] = val;
            else
                Cout[(size_t)m * EE + n] = val;
        }
    }
}

__global__ void qkv_gemm_kernel(const float* __restrict__ q,
                                const float* __restrict__ k,
                                const float* __restrict__ v,
                                const float* __restrict__ Wqkv,
                                const float* __restrict__ bqkv)
{
    int z = blockIdx.z;
    const float* A = (z == 0) ? q : (z == 1) ? k : v;
    gemm_body(A, Wqkv, 3 * EE, z << 10, bqkv, z << 10, nullptr, z);
}

__global__ void out_gemm_kernel(const float* __restrict__ Wout,
                                const float* __restrict__ bout,
                                float* __restrict__ out)
{
    gemm_body(g_ctx, Wout, EE, 0, bout, 0, out, 3);
}

// ---------------------------------------------------------------------------
// Flash attention: Br=64 queries per block, Bc=64 key chunk, 256 threads (16x16),
// each thread owns a 4x4 microtile. Q/K read d-major from scratch (no transpose).
// Row stats reduced across the 16-lane tx group via shfl.
// ---------------------------------------------------------------------------
__global__ void attn_kernel(const int* __restrict__ mask)
{
    extern __shared__ float sm[];
    float* Qs = sm;              // [64][64]  Qs[d][i]
    float* Ks = sm + 4096;       // [64][64]  Ks[d][j]
    float* Vs = sm + 8192;       // [64][64]  Vs[j][d]
    float* Ps = sm + 12288;      // [64][64]  P tile; unioned with mask tile
    int*   Msk = (int*)Ps;

    const int bh = blockIdx.y;       // 0..31
    const int q0 = blockIdx.x << 6;  // query tile start
    const int tid = threadIdx.x;
    const int ty = tid >> 4;
    const int tx = tid & 15;
    const int i0 = ty << 2;
    const int j0 = tx << 2;

    const float* Qbase = g_Qt + (size_t)bh * DD * SS;
    const float* Kbase = g_Kt + (size_t)bh * DD * SS;
    const float* Vbase = g_V + (size_t)bh * SS * DD;

    // load Q tile (d-major -> Qs[d][i]) once
    #pragma unroll
    for (int it = 0; it < 4; ++it) {
        int idx = tid + (it << 8);      // 0..1023
        int d = idx >> 4;
        int c = (idx & 15) << 2;
        *(float4*)&Qs[d * 64 + c] = *(const float4*)(Qbase + (size_t)d * SS + q0 + c);
    }

    float mi[4], li[4], O[4][4];
    #pragma unroll
    for (int i = 0; i < 4; ++i) {
        mi[i] = -1e30f;
        li[i] = 0.f;
        #pragma unroll
        for (int j = 0; j < 4; ++j) O[i][j] = 0.f;
    }

    for (int kc = 0; kc < SS; kc += 64) {
        __syncthreads();   // previous PV reads done before overwrite
        #pragma unroll
        for (int it = 0; it < 4; ++it) {
            int idx = tid + (it << 8);
            int r = idx >> 4;
            int c = (idx & 15) << 2;
            *(float4*)&Ks[r * 64 + c] = *(const float4*)(Kbase + (size_t)r * SS + kc + c);
            *(float4*)&Vs[r * 64 + c] = *(const float4*)(Vbase + (size_t)(kc + r) * DD + c);
            *(int4*)&Msk[r * 64 + c]  = *(const int4*)(mask + (size_t)(q0 + r) * SS + kc + c);
        }
        __syncthreads();

        // S = Q @ K^T  (4x4 per thread)
        float sa[4][4] = {};
        #pragma unroll 16
        for (int d = 0; d < 64; ++d) {
            float4 qv = *(float4*)&Qs[d * 64 + i0];
            float4 kv = *(float4*)&Ks[d * 64 + j0];
            float qa[4] = {qv.x, qv.y, qv.z, qv.w};
            float ka[4] = {kv.x, kv.y, kv.z, kv.w};
            #pragma unroll
            for (int i = 0; i < 4; ++i)
                #pragma unroll
                for (int j = 0; j < 4; ++j)
                    sa[i][j] = fmaf(qa[i], ka[j], sa[i][j]);
        }

        // scale + mask + per-chunk rowmax
        float rm[4];
        #pragma unroll
        for (int i = 0; i < 4; ++i) {
            rm[i] = -1e30f;
            #pragma unroll
            for (int j = 0; j < 4; ++j) {
                float s = sa[i][j] * 0.125f;   // 1/sqrt(64)
                if (Msk[(i0 + i) * 64 + j0 + j] == 0) s = -1e30f;
                sa[i][j] = s;
                rm[i] = fmaxf(rm[i], s);
            }
            rm[i] = fmaxf(rm[i], __shfl_xor_sync(0xffffffffu, rm[i], 8));
            rm[i] = fmaxf(rm[i], __shfl_xor_sync(0xffffffffu, rm[i], 4));
            rm[i] = fmaxf(rm[i], __shfl_xor_sync(0xffffffffu, rm[i], 2));
            rm[i] = fmaxf(rm[i], __shfl_xor_sync(0xffffffffu, rm[i], 1));
        }

        // online softmax update + write P
        #pragma unroll
        for (int i = 0; i < 4; ++i) {
            float mn = fmaxf(mi[i], rm[i]);
            float alpha = __expf(mi[i] - mn);
            mi[i] = mn;
            float rs = 0.f;
            #pragma unroll
            for (int j = 0; j < 4; ++j) {
                float p = __expf(sa[i][j] - mn);
                Ps[(i0 + i) * 64 + j0 + j] = p;
                rs += p;
            }
            rs += __shfl_xor_sync(0xffffffffu, rs, 8);
            rs += __shfl_xor_sync(0xffffffffu, rs, 4);
            rs += __shfl_xor_sync(0xffffffffu, rs, 2);
            rs += __shfl_xor_sync(0xffffffffu, rs, 1);
            li[i] = li[i] * alpha + rs;
            #pragma unroll
            for (int j = 0; j < 4; ++j) O[i][j] *= alpha;
        }
        __syncwarp();   // Ps exchange is within the same warp's 16-lane groups

        // O += P @ V
        #pragma unroll 16
        for (int j = 0; j < 64; ++j) {
            float4 vv = *(float4*)&Vs[j * 64 + j0];
            float va[4] = {vv.x, vv.y, vv.z, vv.w};
            #pragma unroll
            for (int i = 0; i < 4; ++i) {
                float p = Ps[(i0 + i) * 64 + j];
                #pragma unroll
                for (int jj = 0; jj < 4; ++jj)
                    O[i][jj] = fmaf(p, va[jj], O[i][jj]);
            }
        }
    }

    // write ctx [b][s][h*64+d]
    int b = bh >> 4, h = bh & 15;
    #pragma unroll
    for (int i = 0; i < 4; ++i) {
        float inv = 1.0f / li[i];
        size_t rowoff = (size_t)((b << 11) + q0 + i0 + i) * EE + (h << 6) + j0;
        #pragma unroll
        for (int j = 0; j < 4; ++j)
            g_ctx[rowoff + j] = O[i][j] * inv;
    }
}

// ---------------------------------------------------------------------------
extern "C" void kernel_launch(void* const* d_in, const int* in_sizes, int n_in,
                              void* d_out, int out_size)
{
    const float* q    = (const float*)d_in[0];
    const float* k    = (const float*)d_in[1];
    const float* v    = (const float*)d_in[2];
    const int*   mask = (const int*)  d_in[3];
    const float* Wqkv = (const float*)d_in[4];
    const float* bqkv = (const float*)d_in[5];
    const float* Wout = (const float*)d_in[6];
    const float* bout = (const float*)d_in[7];
    float* out = (float*)d_out;

    // 1) fused QKV projection (z selects q/k/v slice of Wqkv)
    qkv_gemm_kernel<<<dim3(8, 32, 3), 256>>>(q, k, v, Wqkv, bqkv);

    // 2) flash attention (64KB dynamic smem)
    cudaFuncSetAttribute(attn_kernel, cudaFuncAttributeMaxDynamicSharedMemorySize, 65536);
    attn_kernel<<<dim3(SS / 64, BB * HH), 256, 65536>>>(mask);

    // 3) output projection
    out_gemm_kernel<<<dim3(8, 32), 256>>>(Wout, bout, out);
}